// round 5
// baseline (speedup 1.0000x reference)
#include <cuda_runtime.h>
#include <cuda_bf16.h>

// LengthRegulator: out[b,t,:] = x[b, searchsorted(cumsum(dur[b]), t, 'right'), :]
// (zeros for t >= total duration). Shapes fixed by the problem:
//   x: [16, 512, 512] f32, durations: [16, 512] i32, out: [16, 4096, 512] f32.
//
// Single fused kernel. Each block re-scans its batch's durations in smem
// (cheap, parallel), then each warp emits 16 consecutive frames with
// register-cached source rows (reload only when the source token changes).

static constexpr int B  = 16;
static constexpr int S  = 512;
static constexpr int H  = 512;
static constexpr int T  = 4096;
static constexpr int H4 = H / 4;              // 128 float4 per row

static constexpr int THREADS          = 256;  // 8 warps
static constexpr int FRAMES_PER_BLOCK = 128;
static constexpr int BLOCKS_PER_BATCH = T / FRAMES_PER_BLOCK;        // 32
static constexpr int FRAMES_PER_WARP  = FRAMES_PER_BLOCK / (THREADS / 32); // 16

__global__ void lr_fused_kernel(const float4* __restrict__ x,
                                const int* __restrict__ durations,
                                float4* __restrict__ out) {
    __shared__ int cum[S];
    __shared__ int wsum[THREADS / 32];
    const int b     = blockIdx.x >> 5;        // / BLOCKS_PER_BATCH
    const int chunk = blockIdx.x & (BLOCKS_PER_BATCH - 1);
    const int tid   = threadIdx.x;
    const int lane  = tid & 31;
    const int wid   = tid >> 5;

    // ── Inclusive scan of dur[b, 0..511] into smem cum[] (2 elems/thread).
    const int d0 = durations[b * S + 2 * tid];
    const int d1 = durations[b * S + 2 * tid + 1];
    int v = d0 + d1;
    #pragma unroll
    for (int off = 1; off < 32; off <<= 1) {
        int n = __shfl_up_sync(0xffffffffu, v, off);
        if (lane >= off) v += n;
    }
    if (lane == 31) wsum[wid] = v;
    __syncthreads();
    if (wid == 0 && lane < 8) {
        int w = wsum[lane];
        #pragma unroll
        for (int off = 1; off < 8; off <<= 1) {
            int n = __shfl_up_sync(0xffu, w, off);
            if (lane >= off) w += n;
        }
        wsum[lane] = w;
    }
    __syncthreads();
    const int incl = v + (wid > 0 ? wsum[wid - 1] : 0);  // inclusive over pair
    cum[2 * tid]     = incl - d1;
    cum[2 * tid + 1] = incl;
    __syncthreads();

    const int total = cum[S - 1];
    const int t0    = chunk * FRAMES_PER_BLOCK + wid * FRAMES_PER_WARP;

    // ── First source token for frame t0: first j with cum[j] > t0.
    int idx;
    {
        int lo = 0, hi = S - 1;
        #pragma unroll
        for (int i = 0; i < 9; ++i) {
            int mid = (lo + hi) >> 1;
            if (cum[mid] > t0) hi = mid; else lo = mid + 1;
        }
        idx = lo;                          // only used while t < total
    }

    const float4 z = make_float4(0.f, 0.f, 0.f, 0.f);
    float4 v0 = z, v1 = z, v2 = z, v3 = z;
    int cur = -1;

    float4* o = out + ((long long)((b << 12) + t0) << 7);
    #pragma unroll 1
    for (int t = t0; t < t0 + FRAMES_PER_WARP; ++t, o += H4) {
        if (t < total) {
            while (cum[idx] <= t) ++idx;   // monotone advance (warp-uniform)
            if (idx != cur) {              // reload row only on token change
                const float4* src = x + ((long long)((b << 9) + idx) << 7);
                v0 = src[lane];      v1 = src[lane + 32];
                v2 = src[lane + 64]; v3 = src[lane + 96];
                cur = idx;
            }
            o[lane]      = v0;  o[lane + 32] = v1;
            o[lane + 64] = v2;  o[lane + 96] = v3;
        } else {
            o[lane]      = z;   o[lane + 32] = z;
            o[lane + 64] = z;   o[lane + 96] = z;
        }
    }
}

extern "C" void kernel_launch(void* const* d_in, const int* in_sizes, int n_in,
                              void* d_out, int out_size) {
    const float* x   = (const float*)d_in[0];      // [B, S, H] f32
    const int*   dur = (const int*)d_in[1];        // [B, S]   i32
    float*       out = (float*)d_out;              // [B, T, H] f32
    (void)in_sizes; (void)n_in; (void)out_size;

    const int blocks = B * BLOCKS_PER_BATCH;       // 512
    lr_fused_kernel<<<blocks, THREADS>>>((const float4*)x, dur, (float4*)out);
}

// round 6
// speedup vs baseline: 1.0471x; 1.0471x over previous
#include <cuda_runtime.h>
#include <cuda_bf16.h>
#include <cstdint>

// LengthRegulator via TMA bulk stores: out[b,t,:] = x[b, idx(t), :].
// x: [16,512,512] f32, durations: [16,512] i32, out: [16,4096,512] f32.
//
// Token-centric: token j owns contiguous frames [cum[j-1], min(cum[j],T)).
// Each copy-CTA stages 16 consecutive token rows (32KB) in smem, then issues
// one cp.async.bulk (2KB, smem->gmem) per output frame — the async engine
// moves the data; the SM store path (L1tex/LSU) is bypassed entirely.

static constexpr int B  = 16;
static constexpr int S  = 512;
static constexpr int H  = 512;
static constexpr int T  = 4096;
static constexpr int H4 = H / 4;                // 128 float4 per row
static constexpr int ROW_BYTES = H * 4;         // 2048

static constexpr int TOK_PER_CTA  = 16;
static constexpr int COPY_CTAS    = B * S / TOK_PER_CTA;   // 512
static constexpr int ZCTA_PER_B   = 8;
static constexpr int ZERO_CTAS    = B * ZCTA_PER_B;        // 128

__device__ int g_start[B * S];
__device__ int g_total[B];

// One block per batch: warp-shuffle inclusive scan; emit exclusive starts.
__global__ void scan_kernel(const int* __restrict__ durations) {
    __shared__ int warp_sums[16];
    const int b    = blockIdx.x;
    const int tid  = threadIdx.x;               // 512
    const int lane = tid & 31;
    const int wid  = tid >> 5;

    const int d = durations[b * S + tid];
    int v = d;
    #pragma unroll
    for (int off = 1; off < 32; off <<= 1) {
        int n = __shfl_up_sync(0xffffffffu, v, off);
        if (lane >= off) v += n;
    }
    if (lane == 31) warp_sums[wid] = v;
    __syncthreads();
    if (wid == 0 && lane < 16) {
        int w = warp_sums[lane];
        #pragma unroll
        for (int off = 1; off < 16; off <<= 1) {
            int n = __shfl_up_sync(0xffffu, w, off);
            if (lane >= off) w += n;
        }
        warp_sums[lane] = w;
    }
    __syncthreads();
    const int cum = v + (wid > 0 ? warp_sums[wid - 1] : 0);
    g_start[b * S + tid] = cum - d;
    if (tid == S - 1) g_total[b] = cum;
}

__device__ __forceinline__ uint32_t smem_u32(const void* p) {
    uint32_t a;
    asm("{ .reg .u64 t; cvta.to.shared.u64 t, %1; cvt.u32.u64 %0, t; }"
        : "=r"(a) : "l"(p));
    return a;
}

__device__ __forceinline__ void bulk_store(void* gmem, uint32_t smem_addr,
                                           uint32_t bytes) {
    asm volatile("cp.async.bulk.global.shared::cta.bulk_group [%0], [%1], %2;"
                 :: "l"(gmem), "r"(smem_addr), "r"(bytes) : "memory");
}

// Blocks [0, COPY_CTAS): stage 16 token rows, bulk-store each frame.
// Blocks [COPY_CTAS, COPY_CTAS+ZERO_CTAS): bulk-store zeros over the tail.
__global__ void __launch_bounds__(128)
expand_tma_kernel(const float4* __restrict__ x,
                  const int* __restrict__ durations,
                  float* __restrict__ out) {
    __shared__ float4 rows[TOK_PER_CTA * H4];   // 32 KB
    const int tid  = threadIdx.x;               // 128
    const int lane = tid & 31;
    const int wid  = tid >> 5;                  // 4 warps

    if (blockIdx.x < COPY_CTAS) {
        const int b  = blockIdx.x / (S / TOK_PER_CTA);         // / 32
        const int j0 = (blockIdx.x % (S / TOK_PER_CTA)) * TOK_PER_CTA;

        // Stage x[b, j0..j0+15, :] (contiguous 32KB): warp w -> rows 4w..4w+3.
        const float4* src = x + ((long long)(b * S + j0) << 7);
        #pragma unroll
        for (int r = 0; r < 4; ++r) {
            const int row = wid * 4 + r;
            #pragma unroll
            for (int q = 0; q < 4; ++q)
                rows[row * H4 + lane + 32 * q] = src[row * H4 + lane + 32 * q];
        }
        __syncthreads();
        asm volatile("fence.proxy.async.shared::cta;" ::: "memory");

        // Owner threads issue one 2KB bulk store per output frame.
        if (tid < TOK_PER_CTA) {
            const int w     = b * S + j0 + tid;
            const int dur   = durations[w];
            const int start = g_start[w];
            int end = start + dur;
            if (end > T) end = T;
            if (start < end) {
                const uint32_t sa = smem_u32(&rows[tid * H4]);
                float* o = out + ((long long)((b << 12) + start) << 9);
                for (int t = start; t < end; ++t, o += H) {
                    bulk_store(o, sa, ROW_BYTES);
                }
                asm volatile("cp.async.bulk.commit_group;" ::: "memory");
                asm volatile("cp.async.bulk.wait_group.read 0;" ::: "memory");
            }
        }
        __syncthreads();                         // smem safe until copies read
    } else {
        // Zero tail: batch b, sub-CTA k strides frames [total+k, T) by 8.
        const int z = blockIdx.x - COPY_CTAS;
        const int b = z >> 3;
        const int k = z & (ZCTA_PER_B - 1);
        // Zero 2KB of smem (one float4 per thread covers 2KB at 128 threads).
        rows[tid] = make_float4(0.f, 0.f, 0.f, 0.f);
        __syncthreads();
        asm volatile("fence.proxy.async.shared::cta;" ::: "memory");

        if (tid == 0) {
            const int total = g_total[b];
            const uint32_t sa = smem_u32(&rows[0]);
            bool issued = false;
            for (int t = total + k; t < T; t += ZCTA_PER_B) {
                float* o = out + ((long long)((b << 12) + t) << 9);
                bulk_store(o, sa, ROW_BYTES);
                issued = true;
            }
            if (issued) {
                asm volatile("cp.async.bulk.commit_group;" ::: "memory");
                asm volatile("cp.async.bulk.wait_group.read 0;" ::: "memory");
            }
        }
        __syncthreads();
    }
}

extern "C" void kernel_launch(void* const* d_in, const int* in_sizes, int n_in,
                              void* d_out, int out_size) {
    const float* x   = (const float*)d_in[0];      // [B, S, H] f32
    const int*   dur = (const int*)d_in[1];        // [B, S]   i32
    float*       out = (float*)d_out;              // [B, T, H] f32
    (void)in_sizes; (void)n_in; (void)out_size;

    scan_kernel<<<B, S>>>(dur);
    expand_tma_kernel<<<COPY_CTAS + ZERO_CTAS, 128>>>(
        (const float4*)x, dur, out);
}

// round 7
// speedup vs baseline: 1.2869x; 1.2290x over previous
#include <cuda_runtime.h>
#include <cuda_bf16.h>

// LengthRegulator: out[b,t,:] = x[b, searchsorted(cumsum(dur[b]), t, 'right'), :]
// (zeros for t >= total duration). Shapes fixed by the problem:
//   x: [16, 512, 512] f32, durations: [16, 512] i32, out: [16, 4096, 512] f32.
//
// R3 structure (best) + streaming stores (__stcs): output is written once and
// read back much later, so evict-first keeps L2 clean and starts DRAM
// writeback immediately instead of bursting it at end-of-kernel.

static constexpr int B  = 16;
static constexpr int S  = 512;
static constexpr int H  = 512;
static constexpr int T  = 4096;
static constexpr int H4 = H / 4;          // 128 float4 per row

// Scratch: per-frame source-token index (S means "invalid / zero frame").
__device__ int g_idx[B * T];

// One block per batch. Warp-shuffle inclusive scan, then scatter: token j
// writes its index over frames [cum[j-1], cum[j]); tail gets S.
__global__ void scan_idx_kernel(const int* __restrict__ durations) {
    __shared__ int warp_sums[16];
    __shared__ int s_total;
    const int b    = blockIdx.x;
    const int tid  = threadIdx.x;         // blockDim.x == S == 512
    const int lane = tid & 31;
    const int wid  = tid >> 5;            // 16 warps

    const int d = durations[b * S + tid];

    int v = d;
    #pragma unroll
    for (int off = 1; off < 32; off <<= 1) {
        int n = __shfl_up_sync(0xffffffffu, v, off);
        if (lane >= off) v += n;
    }
    if (lane == 31) warp_sums[wid] = v;
    __syncthreads();

    if (wid == 0 && lane < 16) {
        int w = warp_sums[lane];
        #pragma unroll
        for (int off = 1; off < 16; off <<= 1) {
            int n = __shfl_up_sync(0xffffu, w, off);
            if (lane >= off) w += n;
        }
        warp_sums[lane] = w;
        if (lane == 15) s_total = w;
    }
    __syncthreads();

    const int cum   = v + (wid > 0 ? warp_sums[wid - 1] : 0);  // inclusive
    const int start = cum - d;                                  // exclusive
    const int total = s_total;
    int* __restrict__ gi = g_idx + b * T;

    for (int t = start; t < cum; ++t) gi[t] = tid;
    for (int t = total + tid; t < T; t += S) gi[t] = S;
}

// One WARP per PAIR of consecutive output rows; 4 float4s per lane per row.
// Warp-uniform idx1==idx0 fast path reuses registers (~87% of pairs).
// All output stores are streaming (evict-first).
__global__ void gather_kernel(const float4* __restrict__ x,
                              float4* __restrict__ out) {
    const int w    = blockIdx.x * (blockDim.x >> 5) + (threadIdx.x >> 5);
    const int row0 = w << 1;              // even; row1 = row0+1 (same batch)
    const int lane = threadIdx.x & 31;
    const int b    = row0 >> 12;          // / T

    const int idx0 = g_idx[row0];
    const int idx1 = g_idx[row0 + 1];

    const float4 z = make_float4(0.f, 0.f, 0.f, 0.f);
    float4 a0 = z, a1 = z, a2 = z, a3 = z;
    float4 c0 = z, c1 = z, c2 = z, c3 = z;

    if (idx0 < S) {
        const float4* s = x + ((long long)((b << 9) + idx0) << 7);
        a0 = s[lane];      a1 = s[lane + 32];
        a2 = s[lane + 64]; a3 = s[lane + 96];
    }
    if (idx1 < S) {
        if (idx1 == idx0) {               // warp-uniform fast path
            c0 = a0; c1 = a1; c2 = a2; c3 = a3;
        } else {
            const float4* s = x + ((long long)((b << 9) + idx1) << 7);
            c0 = s[lane];      c1 = s[lane + 32];
            c2 = s[lane + 64]; c3 = s[lane + 96];
        }
    }

    float4* o0 = out + ((long long)row0 << 7);
    float4* o1 = o0 + H4;
    __stcs(&o0[lane],      a0);  __stcs(&o0[lane + 32], a1);
    __stcs(&o0[lane + 64], a2);  __stcs(&o0[lane + 96], a3);
    __stcs(&o1[lane],      c0);  __stcs(&o1[lane + 32], c1);
    __stcs(&o1[lane + 64], c2);  __stcs(&o1[lane + 96], c3);
}

extern "C" void kernel_launch(void* const* d_in, const int* in_sizes, int n_in,
                              void* d_out, int out_size) {
    const float* x   = (const float*)d_in[0];      // [B, S, H] f32
    const int*   dur = (const int*)d_in[1];        // [B, S]   i32
    float*       out = (float*)d_out;              // [B, T, H] f32
    (void)in_sizes; (void)n_in; (void)out_size;

    scan_idx_kernel<<<B, S>>>(dur);

    const int threads = 256;                        // 8 warps = 16 rows/block
    const int blocks  = (B * T) / ((threads / 32) * 2);  // 4096
    gather_kernel<<<blocks, threads>>>((const float4*)x, (float4*)out);
}